// round 15
// baseline (speedup 1.0000x reference)
#include <cuda_runtime.h>
#include <cuda_fp16.h>
#include <cstdint>
#include <math.h>

#define SQ 1024
#define DM 2048
#define NH 8
#define DKV 128
#define HDIM 1024
#define NE 16
#define TOPK 6
#define FF 1408
#define FSH 2816
#define NSLOT (SQ*TOPK)

// fp32 scratch
__device__ float g_q[SQ*HDIM];
__device__ float g_k[SQ*HDIM];
__device__ float g_v[SQ*HDIM];
__device__ float g_sc[NH*SQ*SQ];
__device__ float g_x2[SQ*DM];
__device__ float g_ln2[SQ*DM];
__device__ float g_t1[SQ*FSH];
__device__ float g_h1[NSLOT*FF];
// half planes: activations (hi only)
__device__ __half a_ln_h[SQ*DM];
__device__ __half a_at_h[SQ*HDIM];
__device__ __half a_l2_h[SQ*DM];
__device__ __half a_hs_h[SQ*FSH];
__device__ __half a_hh_h[NSLOT*FF];
// half planes: weights transposed to [N][K], hi + lo (exact-weight 2-term)
__device__ __half w_q_h[HDIM*DM];  __device__ __half w_q_l[HDIM*DM];
__device__ __half w_k_h[HDIM*DM];  __device__ __half w_k_l[HDIM*DM];
__device__ __half w_v_h[HDIM*DM];  __device__ __half w_v_l[HDIM*DM];
__device__ __half w_o_h[DM*HDIM];  __device__ __half w_o_l[DM*HDIM];
__device__ __half w_s1_h[FSH*DM];  __device__ __half w_s1_l[FSH*DM];
__device__ __half w_s3_h[FSH*DM];  __device__ __half w_s3_l[FSH*DM];
__device__ __half w_s2_h[DM*FSH];  __device__ __half w_s2_l[DM*FSH];
__device__ __half w_e1_h[NE*FF*DM];__device__ __half w_e1_l[NE*FF*DM];
__device__ __half w_e3_h[NE*FF*DM];__device__ __half w_e3_l[NE*FF*DM];
__device__ __half w_e2_h[NE*DM*FF];__device__ __half w_e2_l[NE*DM*FF];
// routing
__device__ int   g_idx[SQ*TOPK];
__device__ float g_wt[SQ*TOPK];
__device__ int   g_cnt[NE];
__device__ int   g_off[NE];
__device__ int   g_pos[NE];
__device__ int   g_tok[NSLOT];
__device__ float g_wa[NSLOT];

struct QKVH { const __half* bh[3]; const __half* bl[3]; const float* bias[3]; float* c[3]; };

__device__ __forceinline__ uint32_t smem_u32(const void* p){
    uint32_t a;
    asm("{ .reg .u64 t; cvta.to.shared.u64 t, %1; cvt.u32.u64 %0, t; }":"=r"(a):"l"(p));
    return a;
}
__device__ __forceinline__ void cpa16(uint32_t dst, const void* src, int sz){
    asm volatile("cp.async.cg.shared.global [%0],[%1],16,%2;"
                 ::"r"(dst),"l"(src),"r"(sz):"memory");
}
__device__ __forceinline__ void mma16(float* c, const uint32_t* a, const uint32_t* b){
    asm volatile("mma.sync.aligned.m16n8k16.row.col.f32.f16.f16.f32 "
        "{%0,%1,%2,%3},{%4,%5,%6,%7},{%8,%9},{%0,%1,%2,%3};"
        :"+f"(c[0]),"+f"(c[1]),"+f"(c[2]),"+f"(c[3])
        :"r"(a[0]),"r"(a[1]),"r"(a[2]),"r"(a[3]),"r"(b[0]),"r"(b[1]));
}
#define LDSM4(r, a) \
    asm volatile("ldmatrix.sync.aligned.m8n8.x4.shared.b16 {%0,%1,%2,%3},[%4];" \
        :"=r"((r)[0]),"=r"((r)[1]),"=r"((r)[2]),"=r"((r)[3]):"r"(a))

// smem: 3 planes (Ah, Bh, Bl), 128 rows x 128 halves (256B) padded to 272B/row
#define KC 128
#define RSTR 272
#define PLANE (128*RSTR)          // 34816
#define BUFB (3*PLANE)            // 104448
#define DSM (2*BUFB)              // 208896 (~204KB, 1 CTA/SM)

// MODE 0: plain. MODE 1: token-gather A (slot out). MODE 2: slot A -> weighted scatter.
// MODE 3: QKV fused. CTA 128x128, 256 thr, warps 2m x 4n, warp tile 64x32.
// 2-term: fp16 activations x exact weights (a*bh + a*bl).
template<int MODE>
__global__ __launch_bounds__(256) void hgemm(
    const __half* __restrict__ Ah,
    const __half* __restrict__ Bh, const __half* __restrict__ Bl,
    const float* __restrict__ bias, const float* __restrict__ res,
    const float* __restrict__ comp, float* __restrict__ Cf,
    __half* __restrict__ Ch,
    int N, int Kd, QKVH q3)
{
    extern __shared__ __align__(16) char sm[];
    const int tid = threadIdx.x, wid = tid>>5, lane = tid&31;
    const int warp_m = wid&1, warp_n = wid>>1;
    const int bm = blockIdx.y*128, bn = blockIdx.x*128;
    int count = 1<<30, base = 0;
    if (MODE == 1 || MODE == 2){
        int e = blockIdx.z;
        count = g_cnt[e]; base = g_off[e];
        if (bm >= count) return;
        Bh += (size_t)e*N*Kd; Bl += (size_t)e*N*Kd;
        bias += (size_t)e*N;
    }
    if (MODE == 3){
        int z = blockIdx.z;
        Bh = q3.bh[z]; Bl = q3.bl[z]; bias = q3.bias[z]; Cf = q3.c[z];
    }
    // A row pointers: 4 rows per thread (sr+32i); each thread covers 32B x2 per row
    const int sr = tid>>3;
    const int ac = (tid&7)*16;            // element offset (halves): 8 chunks of 16
    const __half* pAh[4]; int avv[4];
#pragma unroll
    for (int i = 0; i < 4; i++){
        int row = bm + sr + 32*i;
        avv[i] = 16;
        if (MODE == 1){
            bool v = row < count;
            avv[i] = v ? 16 : 0;
            pAh[i] = Ah + (size_t)(v ? g_tok[base+row] : 0)*Kd;
        } else if (MODE == 2){
            pAh[i] = Ah + (size_t)(base + (row < count ? row : count-1))*Kd;
        } else {
            pAh[i] = Ah + (size_t)row*Kd;
        }
    }
    const uint32_t smu = smem_u32(sm);
    const uint32_t sdst = smu + (uint32_t)sr*RSTR + (uint32_t)ac*2u;
    // ldmatrix lane bases
    const int mat = lane>>3, l7 = lane&7;
    const uint32_t a_lm = smu
        + (uint32_t)((warp_m*64 + (mat&1)*8 + l7)*RSTR + (mat>>1)*16);
    const uint32_t b_lm = smu + PLANE
        + (uint32_t)((warp_n*32 + (mat>>1)*8 + l7)*RSTR + (mat&1)*16);

    const int nch = Kd/KC;
    // prologue: chunk 0 -> buf 0
#pragma unroll
    for (int i = 0; i < 4; i++){
        uint32_t d = sdst + (uint32_t)(32*i)*RSTR;
        size_t bro = (size_t)(bn+sr+32*i)*Kd;
        cpa16(d,              pAh[i] + ac,     avv[i]);
        cpa16(d + 16,         pAh[i] + ac + 8, avv[i]);
        cpa16(d + PLANE,      Bh + bro + ac,     16);
        cpa16(d + PLANE + 16, Bh + bro + ac + 8, 16);
        cpa16(d + 2*PLANE,      Bl + bro + ac,     16);
        cpa16(d + 2*PLANE + 16, Bl + bro + ac + 8, 16);
    }
    asm volatile("cp.async.commit_group;":::"memory");

    float acc[4][4][4];
#pragma unroll
    for (int a = 0; a < 4; a++)
#pragma unroll
        for (int b = 0; b < 4; b++)
#pragma unroll
            for (int r = 0; r < 4; r++) acc[a][b][r] = 0.f;

    for (int c = 0; c < nch; c++){
        const uint32_t bufo = (uint32_t)(c&1)*BUFB;
        if (c+1 < nch){
            const uint32_t nb = (uint32_t)((c+1)&1)*BUFB;
            const int k0 = (c+1)*KC;
#pragma unroll
            for (int i = 0; i < 4; i++){
                uint32_t d = sdst + nb + (uint32_t)(32*i)*RSTR;
                size_t bro = (size_t)(bn+sr+32*i)*Kd + k0;
                cpa16(d,              pAh[i] + k0 + ac,     avv[i]);
                cpa16(d + 16,         pAh[i] + k0 + ac + 8, avv[i]);
                cpa16(d + PLANE,      Bh + bro + ac,     16);
                cpa16(d + PLANE + 16, Bh + bro + ac + 8, 16);
                cpa16(d + 2*PLANE,      Bl + bro + ac,     16);
                cpa16(d + 2*PLANE + 16, Bl + bro + ac + 8, 16);
            }
            asm volatile("cp.async.commit_group;":::"memory");
            asm volatile("cp.async.wait_group 1;":::"memory");
        } else {
            asm volatile("cp.async.wait_group 0;":::"memory");
        }
        __syncthreads();
#pragma unroll
        for (int ks = 0; ks < KC/16; ks++){
            uint32_t ah[4][4], bh4[2][4], bl4[2][4];
#pragma unroll
            for (int mf = 0; mf < 4; mf++)
                LDSM4(ah[mf], a_lm + bufo + mf*(16*RSTR) + ks*32);
#pragma unroll
            for (int np = 0; np < 2; np++){
                LDSM4(bh4[np], b_lm + bufo + np*(16*RSTR) + ks*32);
                LDSM4(bl4[np], b_lm + bufo + PLANE + np*(16*RSTR) + ks*32);
            }
            // term-grouped: 16 independent hh, then 16 hl
#pragma unroll
            for (int np = 0; np < 2; np++)
#pragma unroll
                for (int mf = 0; mf < 4; mf++)
#pragma unroll
                    for (int j = 0; j < 2; j++)
                        mma16(acc[mf][np*2+j], ah[mf], &bh4[np][j*2]);
#pragma unroll
            for (int np = 0; np < 2; np++)
#pragma unroll
                for (int mf = 0; mf < 4; mf++)
#pragma unroll
                    for (int j = 0; j < 2; j++)
                        mma16(acc[mf][np*2+j], ah[mf], &bl4[np][j*2]);
        }
        __syncthreads();
    }

    // epilogue
    const int qr = lane>>2, qc = lane&3;
#pragma unroll
    for (int mf = 0; mf < 4; mf++){
#pragma unroll
        for (int hf = 0; hf < 2; hf++){
            int rl = warp_m*64 + mf*16 + qr + hf*8;
            bool rv = true; size_t crow = (size_t)(bm + rl); float ws = 1.f;
            if (MODE == 1){ rv = (bm + rl) < count; crow = (size_t)(base + bm + rl); }
            if (MODE == 2){
                rv = (bm + rl) < count;
                int s2 = rv ? (base + bm + rl) : base;
                crow = (size_t)g_tok[s2]; ws = g_wa[s2];
            }
            if (!rv) continue;
#pragma unroll
            for (int nf = 0; nf < 4; nf++){
                int col = bn + warp_n*32 + nf*8 + qc*2;
                float v0 = acc[mf][nf][hf*2+0] + bias[col];
                float v1 = acc[mf][nf][hf*2+1] + bias[col+1];
                if (comp){
                    float c0 = comp[crow*N + col], c1 = comp[crow*N + col + 1];
                    v0 *= c0/(1.f+__expf(-c0));
                    v1 *= c1/(1.f+__expf(-c1));
                }
                if (MODE == 2){
                    atomicAdd(Cf + crow*N + col,     ws*v0);
                    atomicAdd(Cf + crow*N + col + 1, ws*v1);
                } else if (Ch){
                    __half2 h2 = __floats2half2_rn(v0, v1);
                    *(uint32_t*)(Ch + crow*N + col) = *reinterpret_cast<uint32_t*>(&h2);
                } else {
                    if (res){ v0 += res[crow*N + col]; v1 += res[crow*N + col + 1]; }
                    *(float2*)(Cf + crow*N + col) = make_float2(v0, v1);
                }
            }
        }
    }
}

// ---------------- weight transpose + split (hi + lo) -----------------------------
__global__ __launch_bounds__(256) void wsplitT(const float* __restrict__ in,
                                               __half* __restrict__ oh,
                                               __half* __restrict__ ol, int K, int N)
{
    __shared__ float s[32][33];
    size_t bo = (size_t)blockIdx.z * K * N;
    in += bo; oh += bo; ol += bo;
    int n0 = blockIdx.x*32, k0 = blockIdx.y*32;
    int tx = threadIdx.x & 31, ty = threadIdx.x >> 5;
#pragma unroll
    for (int i = 0; i < 4; i++)
        s[ty + 8*i][tx] = in[(size_t)(k0 + ty + 8*i)*N + n0 + tx];
    __syncthreads();
    int n = threadIdx.x >> 3, cc = threadIdx.x & 7;
    uint32_t hw[2], lw[2];
#pragma unroll
    for (int p = 0; p < 2; p++){
        float x0 = s[cc*4 + p*2 + 0][n], x1 = s[cc*4 + p*2 + 1][n];
        __half2 h2 = __floats2half2_rn(x0, x1);
        float2 hf = __half22float2(h2);
        __half2 l2 = __floats2half2_rn(x0 - hf.x, x1 - hf.y);
        hw[p] = *reinterpret_cast<uint32_t*>(&h2);
        lw[p] = *reinterpret_cast<uint32_t*>(&l2);
    }
    size_t o = (size_t)(n0 + n)*K + k0 + cc*4;
    *(uint2*)(oh + o) = make_uint2(hw[0], hw[1]);
    *(uint2*)(ol + o) = make_uint2(lw[0], lw[1]);
}

// ---------------- SIMT parts ----------------
__device__ __forceinline__ void mma_step(const float (*As)[64], const float (*Bs)[64],
                                         float acc[4][4], int ty4, int tx4)
{
#pragma unroll
    for (int kk = 0; kk < 16; kk++){
        float a[4], b[4];
#pragma unroll
        for (int i = 0; i < 4; i++) a[i] = As[kk][ty4+i];
#pragma unroll
        for (int j = 0; j < 4; j++) b[j] = Bs[kk][tx4+j];
#pragma unroll
        for (int i = 0; i < 4; i++)
#pragma unroll
            for (int j = 0; j < 4; j++) acc[i][j] = fmaf(a[i], b[j], acc[i][j]);
    }
}

__global__ __launch_bounds__(256) void ln_kernel(const float* __restrict__ x,
                                                 const float* __restrict__ g,
                                                 float* __restrict__ of,
                                                 __half* __restrict__ oh)
{
    __shared__ float red[256];
    const int row = blockIdx.x, t = threadIdx.x;
    const float* xr = x + (size_t)row*DM;
    float s = 0.f;
    for (int i = t; i < DM; i += 256) s += xr[i];
    red[t] = s; __syncthreads();
    for (int k = 128; k > 0; k >>= 1){ if (t < k) red[t] += red[t+k]; __syncthreads(); }
    const float mu = red[0]*(1.f/DM); __syncthreads();
    float v = 0.f;
    for (int i = t; i < DM; i += 256){ float d0 = xr[i]-mu; v += d0*d0; }
    red[t] = v; __syncthreads();
    for (int k = 128; k > 0; k >>= 1){ if (t < k) red[t] += red[t+k]; __syncthreads(); }
    const float inv = rsqrtf(red[0]*(1.f/DM) + 1e-8f);
    for (int i = t; i < DM; i += 256){
        float val = (xr[i]-mu)*inv*g[i];
        size_t o = (size_t)row*DM + i;
        if (of) of[o] = val;
        oh[o] = __float2half_rn(val);
    }
}

__global__ __launch_bounds__(256) void score_kernel(const float* __restrict__ mask)
{
    if (blockIdx.x > blockIdx.y) return;   // fully masked (causal)
    __shared__ float As[16][64];
    __shared__ float Bs[16][64];
    const int h = blockIdx.z, bi = blockIdx.y*64, bj = blockIdx.x*64;
    const int tid = threadIdx.x;
    const int tx4 = (tid&15)*4, ty4 = (tid>>4)*4;
    const int am = tid>>2, ak = (tid&3)*4;
    float acc[4][4] = {};
    const float* qp = g_q + (size_t)(bi+am)*HDIM + h*DKV + ak;
    const float* kp = g_k + (size_t)(bj+am)*HDIM + h*DKV + ak;
    for (int k0 = 0; k0 < DKV; k0 += 16){
        float4 a = *(const float4*)(qp+k0);
        As[ak+0][am]=a.x; As[ak+1][am]=a.y; As[ak+2][am]=a.z; As[ak+3][am]=a.w;
        float4 b = *(const float4*)(kp+k0);
        Bs[ak+0][am]=b.x; Bs[ak+1][am]=b.y; Bs[ak+2][am]=b.z; Bs[ak+3][am]=b.w;
        __syncthreads();
        mma_step(As, Bs, acc, ty4, tx4);
        __syncthreads();
    }
    const float slope = exp2f(-(float)(h+1));
    const float sc = 0.08838834764831845f;
#pragma unroll
    for (int i = 0; i < 4; i++){
        int gi = bi+ty4+i;
#pragma unroll
        for (int j = 0; j < 4; j++){
            int gj = bj+tx4+j;
            float al = (gi >= gj) ? -(float)(gi-gj)*slope : 0.f;
            g_sc[((size_t)h*SQ+gi)*SQ+gj] = acc[i][j]*sc + al + mask[(size_t)gi*SQ+gj];
        }
    }
}

__global__ __launch_bounds__(256) void softmax_kernel()
{
    __shared__ float red[256];
    float* r = g_sc + (size_t)blockIdx.x*SQ;
    const int i = blockIdx.x & (SQ-1);
    const int t = threadIdx.x;
    const int j0 = 4*t;
    float4 v = ((float4*)r)[t];
    float m0 = (j0+0 <= i) ? v.x : -1e30f;
    float m1 = (j0+1 <= i) ? v.y : -1e30f;
    float m2 = (j0+2 <= i) ? v.z : -1e30f;
    float m3 = (j0+3 <= i) ? v.w : -1e30f;
    float m = fmaxf(fmaxf(m0,m1), fmaxf(m2,m3));
    red[t] = m; __syncthreads();
    for (int k = 128; k > 0; k >>= 1){ if (t < k) red[t] = fmaxf(red[t], red[t+k]); __syncthreads(); }
    m = red[0]; __syncthreads();
    float4 e;
    e.x = (j0+0 <= i) ? __expf(v.x-m) : 0.f;
    e.y = (j0+1 <= i) ? __expf(v.y-m) : 0.f;
    e.z = (j0+2 <= i) ? __expf(v.z-m) : 0.f;
    e.w = (j0+3 <= i) ? __expf(v.w-m) : 0.f;
    red[t] = e.x+e.y+e.z+e.w; __syncthreads();
    for (int k = 128; k > 0; k >>= 1){ if (t < k) red[t] += red[t+k]; __syncthreads(); }
    const float inv = 1.f/red[0];
    e.x*=inv; e.y*=inv; e.z*=inv; e.w*=inv;
    ((float4*)r)[t] = e;
}

__global__ __launch_bounds__(256) void pv_kernel()
{
    __shared__ float As[16][64];
    __shared__ float Bs[16][64];
    const int h = blockIdx.z, bm = blockIdx.y*64, bn = blockIdx.x*64;
    const int tid = threadIdx.x;
    const int tx4 = (tid&15)*4, ty4 = (tid>>4)*4;
    const int bkr = tid>>4, bc = (tid&15)*4;
    float acc[4][4] = {};
    const float* Pp = g_sc + (size_t)h*SQ*SQ + (size_t)bkr*SQ + bm + bc;
    const float* Vp = g_v + (size_t)bkr*HDIM + h*DKV + bn + bc;
    for (int k0 = bm; k0 < SQ; k0 += 16){
        *(float4*)(&As[bkr][bc]) = *(const float4*)(Pp + (size_t)k0*SQ);
        *(float4*)(&Bs[bkr][bc]) = *(const float4*)(Vp + (size_t)k0*HDIM);
        __syncthreads();
        mma_step(As, Bs, acc, ty4, tx4);
        __syncthreads();
    }
#pragma unroll
    for (int i = 0; i < 4; i++){
        size_t rb = (size_t)(bm+ty4+i)*HDIM + h*DKV + bn + tx4;
#pragma unroll
        for (int j = 0; j < 4; j += 2){
            __half2 h2 = __floats2half2_rn(acc[i][j], acc[i][j+1]);
            *(uint32_t*)(a_at_h + rb + j) = *reinterpret_cast<uint32_t*>(&h2);
        }
    }
}

__global__ void reset_kernel(){
    int t = threadIdx.x;
    if (t < NE){ g_cnt[t] = 0; g_pos[t] = 0; }
}

__global__ __launch_bounds__(256) void gate_kernel(const float* __restrict__ xf,
                                                   const float* __restrict__ gw,
                                                   const float* __restrict__ gb)
{
    __shared__ float xs[DM];
    __shared__ float lg[NE];
    const int tok = blockIdx.x, tid = threadIdx.x;
    for (int i = tid; i < DM; i += 256) xs[i] = xf[(size_t)tok*DM+i];
    __syncthreads();
    const int warp = tid>>5, lane = tid&31;
    for (int e = warp; e < NE; e += 8){
        const float* w = gw + (size_t)e*DM;
        float s = 0.f;
        for (int i = lane; i < DM; i += 32) s += xs[i]*w[i];
        for (int o = 16; o; o >>= 1) s += __shfl_down_sync(0xFFFFFFFFu, s, o);
        if (lane == 0) lg[e] = s;
    }
    __syncthreads();
    if (tid == 0){
        float mx = -1e30f;
        for (int e = 0; e < NE; e++) mx = fmaxf(mx, lg[e]);
        float sm[NE], se = 0.f;
        for (int e = 0; e < NE; e++){ sm[e] = expf(lg[e]-mx); se += sm[e]; }
        float inv = 1.f/se;
        for (int e = 0; e < NE; e++) sm[e] *= inv;
        bool used[NE] = {};
        for (int kk = 0; kk < TOPK; kk++){
            float best = -1e30f; int bi = 0;
            for (int e = 0; e < NE; e++)
                if (!used[e]){ float s = sm[e]+gb[e]; if (s > best){ best = s; bi = e; } }
            used[bi] = true;
            g_idx[tok*TOPK+kk] = bi;
            g_wt[tok*TOPK+kk] = sm[bi];
            atomicAdd(&g_cnt[bi], 1);
        }
    }
}

// merged scan + place (single block)
__global__ __launch_bounds__(256) void scanplace_kernel(){
    __shared__ int off_s[NE];
    if (threadIdx.x == 0){
        int r = 0;
        for (int e = 0; e < NE; e++){ off_s[e] = r; g_off[e] = r; r += g_cnt[e]; }
    }
    __syncthreads();
    for (int t = threadIdx.x; t < SQ; t += 256){
        for (int kk = 0; kk < TOPK; kk++){
            int e = g_idx[t*TOPK+kk];
            int p = off_s[e] + atomicAdd(&g_pos[e], 1);
            g_tok[p] = t;
            g_wa[p] = g_wt[t*TOPK+kk];
        }
    }
}

#define SYM(var, name) cudaGetSymbolAddress((void**)&var, name)

extern "C" void kernel_launch(void* const* d_in, const int* in_sizes, int n_in,
                              void* d_out, int out_size)
{
    const float* x      = (const float*)d_in[0];
    const float* mask   = (const float*)d_in[1];
    const float* attn_g = (const float*)d_in[2];
    const float* wq_w   = (const float*)d_in[3];
    const float* wq_b   = (const float*)d_in[4];
    const float* wk_w   = (const float*)d_in[5];
    const float* wk_b   = (const float*)d_in[6];
    const float* wv_w   = (const float*)d_in[7];
    const float* wv_b   = (const float*)d_in[8];
    const float* wo_w   = (const float*)d_in[9];
    const float* wo_b   = (const float*)d_in[10];
    const float* ffn_g  = (const float*)d_in[11];
    const float* gate_w = (const float*)d_in[12];
    const float* gate_b = (const float*)d_in[13];
    const float* e_w1   = (const float*)d_in[14];
    const float* e_b1   = (const float*)d_in[15];
    const float* e_w2   = (const float*)d_in[16];
    const float* e_b2   = (const float*)d_in[17];
    const float* e_w3   = (const float*)d_in[18];
    const float* e_b3   = (const float*)d_in[19];
    const float* s_w1   = (const float*)d_in[20];
    const float* s_b1   = (const float*)d_in[21];
    const float* s_w2   = (const float*)d_in[22];
    const float* s_b2   = (const float*)d_in[23];
    const float* s_w3   = (const float*)d_in[24];
    const float* s_b3   = (const float*)d_in[25];
    float* outp = (float*)d_out;

    float *p_q,*p_k,*p_v,*p_x2,*p_ln2,*p_t1,*p_h1;
    SYM(p_q, g_q); SYM(p_k, g_k); SYM(p_v, g_v);
    SYM(p_x2, g_x2); SYM(p_ln2, g_ln2); SYM(p_t1, g_t1); SYM(p_h1, g_h1);
    __half *lnH,*atH,*l2H,*hsH,*hhH;
    SYM(lnH, a_ln_h); SYM(atH, a_at_h); SYM(l2H, a_l2_h);
    SYM(hsH, a_hs_h); SYM(hhH, a_hh_h);
    __half *wqH,*wqL,*wkH,*wkL,*wvH,*wvL,*woH,*woL;
    __half *s1H,*s1L,*s3H,*s3L,*s2H,*s2L,*e1H,*e1L,*e3H,*e3L,*e2H,*e2L;
    SYM(wqH, w_q_h); SYM(wqL, w_q_l); SYM(wkH, w_k_h); SYM(wkL, w_k_l);
    SYM(wvH, w_v_h); SYM(wvL, w_v_l); SYM(woH, w_o_h); SYM(woL, w_o_l);
    SYM(s1H, w_s1_h); SYM(s1L, w_s1_l); SYM(s3H, w_s3_h); SYM(s3L, w_s3_l);
    SYM(s2H, w_s2_h); SYM(s2L, w_s2_l);
    SYM(e1H, w_e1_h); SYM(e1L, w_e1_l); SYM(e3H, w_e3_h); SYM(e3L, w_e3_l);
    SYM(e2H, w_e2_h); SYM(e2L, w_e2_l);

    cudaFuncSetAttribute(hgemm<0>, cudaFuncAttributeMaxDynamicSharedMemorySize, DSM);
    cudaFuncSetAttribute(hgemm<1>, cudaFuncAttributeMaxDynamicSharedMemorySize, DSM);
    cudaFuncSetAttribute(hgemm<2>, cudaFuncAttributeMaxDynamicSharedMemorySize, DSM);
    cudaFuncSetAttribute(hgemm<3>, cudaFuncAttributeMaxDynamicSharedMemorySize, DSM);

    // side stream for ALL weight splits: attention splits first (join ev2),
    // then expert/shared splits (join ev1). Overlaps ln / attention phase.
    static cudaStream_t s1 = nullptr;
    static cudaEvent_t ev0 = nullptr, ev1 = nullptr, ev2 = nullptr;
    if (!s1){
        cudaStreamCreateWithFlags(&s1, cudaStreamNonBlocking);
        cudaEventCreateWithFlags(&ev0, cudaEventDisableTiming);
        cudaEventCreateWithFlags(&ev1, cudaEventDisableTiming);
        cudaEventCreateWithFlags(&ev2, cudaEventDisableTiming);
    }
    cudaEventRecord(ev0, 0);
    cudaStreamWaitEvent(s1, ev0, 0);
    // attention-path splits (needed first)
    wsplitT<<<dim3(HDIM/32, DM/32, 1), 256, 0, s1>>>(wq_w, wqH, wqL, DM, HDIM);
    wsplitT<<<dim3(HDIM/32, DM/32, 1), 256, 0, s1>>>(wk_w, wkH, wkL, DM, HDIM);
    wsplitT<<<dim3(HDIM/32, DM/32, 1), 256, 0, s1>>>(wv_w, wvH, wvL, DM, HDIM);
    wsplitT<<<dim3(DM/32, HDIM/32, 1), 256, 0, s1>>>(wo_w, woH, woL, HDIM, DM);
    cudaEventRecord(ev2, s1);
    // expert/shared splits
    wsplitT<<<dim3(FSH/32, DM/32, 1), 256, 0, s1>>>(s_w1, s1H, s1L, DM, FSH);
    wsplitT<<<dim3(FSH/32, DM/32, 1), 256, 0, s1>>>(s_w3, s3H, s3L, DM, FSH);
    wsplitT<<<dim3(DM/32, FSH/32, 1), 256, 0, s1>>>(s_w2, s2H, s2L, FSH, DM);
    wsplitT<<<dim3(FF/32, DM/32, NE), 256, 0, s1>>>(e_w1, e1H, e1L, DM, FF);
    wsplitT<<<dim3(FF/32, DM/32, NE), 256, 0, s1>>>(e_w3, e3H, e3L, DM, FF);
    wsplitT<<<dim3(DM/32, FF/32, NE), 256, 0, s1>>>(e_w2, e2H, e2L, FF, DM);
    cudaEventRecord(ev1, s1);

    QKVH z3 = {};
    QKVH qkv;
    qkv.bh[0]=wqH; qkv.bh[1]=wkH; qkv.bh[2]=wvH;
    qkv.bl[0]=wqL; qkv.bl[1]=wkL; qkv.bl[2]=wvL;
    qkv.bias[0]=wq_b; qkv.bias[1]=wk_b; qkv.bias[2]=wv_b;
    qkv.c[0]=p_q; qkv.c[1]=p_k; qkv.c[2]=p_v;

    // ---- attention ----
    ln_kernel<<<SQ, 256>>>(x, attn_g, nullptr, lnH);
    cudaStreamWaitEvent(0, ev2, 0);
    hgemm<3><<<dim3(HDIM/128, SQ/128, 3), 256, DSM>>>(lnH, nullptr, nullptr,
        nullptr, nullptr, nullptr, nullptr, nullptr, HDIM, DM, qkv);
    score_kernel<<<dim3(SQ/64, SQ/64, NH), 256>>>(mask);
    softmax_kernel<<<NH*SQ, 256>>>();
    pv_kernel<<<dim3(DKV/64, SQ/64, NH), 256>>>();
    hgemm<0><<<dim3(DM/128, SQ/128), 256, DSM>>>(atH, woH, woL,
        wo_b, x, nullptr, p_x2, nullptr, DM, HDIM, z3);

    // ---- moe routing ----
    ln_kernel<<<SQ, 256>>>(p_x2, ffn_g, p_ln2, l2H);
    reset_kernel<<<1, 32>>>();
    gate_kernel<<<SQ, 256>>>(p_ln2, gate_w, gate_b);
    scanplace_kernel<<<1, 256>>>();

    // join side-stream splits before MoE GEMMs
    cudaStreamWaitEvent(0, ev1, 0);

    // ---- shared expert ----
    hgemm<0><<<dim3(FSH/128, SQ/128), 256, DSM>>>(l2H, s1H, s1L,
        s_b1, nullptr, nullptr, p_t1, nullptr, FSH, DM, z3);
    hgemm<0><<<dim3(FSH/128, SQ/128), 256, DSM>>>(l2H, s3H, s3L,
        s_b3, nullptr, p_t1, nullptr, hsH, FSH, DM, z3);
    hgemm<0><<<dim3(DM/128, SQ/128), 256, DSM>>>(hsH, s2H, s2L,
        s_b2, p_x2, nullptr, outp, nullptr, DM, FSH, z3);

    // ---- routed experts ----
    hgemm<1><<<dim3(FF/128, SQ/128, NE), 256, DSM>>>(l2H, e1H, e1L,
        e_b1, nullptr, nullptr, p_h1, nullptr, FF, DM, z3);
    hgemm<1><<<dim3(FF/128, SQ/128, NE), 256, DSM>>>(l2H, e3H, e3L,
        e_b3, nullptr, p_h1, nullptr, hhH, FF, DM, z3);
    hgemm<2><<<dim3(DM/128, SQ/128, NE), 256, DSM>>>(hhH, e2H, e2L,
        e_b2, nullptr, nullptr, outp, nullptr, DM, FF, z3);
}

// round 16
// speedup vs baseline: 1.0806x; 1.0806x over previous
#include <cuda_runtime.h>
#include <cuda_fp16.h>
#include <cstdint>
#include <math.h>

#define SQ 1024
#define DM 2048
#define NH 8
#define DKV 128
#define HDIM 1024
#define NE 16
#define TOPK 6
#define FF 1408
#define FSH 2816
#define NSLOT (SQ*TOPK)

// fp32 scratch
__device__ float g_q[SQ*HDIM];
__device__ float g_k[SQ*HDIM];
__device__ float g_v[SQ*HDIM];
__device__ float g_sc[NH*SQ*SQ];
__device__ float g_x2[SQ*DM];
__device__ float g_ln2[SQ*DM];
__device__ float g_t1[SQ*FSH];
__device__ float g_h1[NSLOT*FF];
// half planes: activations (hi only)
__device__ __half a_ln_h[SQ*DM];
__device__ __half a_at_h[SQ*HDIM];
__device__ __half a_l2_h[SQ*DM];
__device__ __half a_hs_h[SQ*FSH];
__device__ __half a_hh_h[NSLOT*FF];
// half planes: weights transposed to [N][K], hi + lo (exact-weight 2-term)
__device__ __half w_q_h[HDIM*DM];  __device__ __half w_q_l[HDIM*DM];
__device__ __half w_k_h[HDIM*DM];  __device__ __half w_k_l[HDIM*DM];
__device__ __half w_v_h[HDIM*DM];  __device__ __half w_v_l[HDIM*DM];
__device__ __half w_o_h[DM*HDIM];  __device__ __half w_o_l[DM*HDIM];
__device__ __half w_s1_h[FSH*DM];  __device__ __half w_s1_l[FSH*DM];
__device__ __half w_s3_h[FSH*DM];  __device__ __half w_s3_l[FSH*DM];
__device__ __half w_s2_h[DM*FSH];  __device__ __half w_s2_l[DM*FSH];
__device__ __half w_e1_h[NE*FF*DM];__device__ __half w_e1_l[NE*FF*DM];
__device__ __half w_e3_h[NE*FF*DM];__device__ __half w_e3_l[NE*FF*DM];
__device__ __half w_e2_h[NE*DM*FF];__device__ __half w_e2_l[NE*DM*FF];
// routing
__device__ int   g_idx[SQ*TOPK];
__device__ float g_wt[SQ*TOPK];
__device__ int   g_cnt[NE];
__device__ int   g_off[NE];
__device__ int   g_pos[NE];
__device__ int   g_tok[NSLOT];
__device__ float g_wa[NSLOT];

struct QKVH { const __half* bh[3]; const __half* bl[3]; const float* bias[3]; float* c[3]; };

__device__ __forceinline__ uint32_t smem_u32(const void* p){
    uint32_t a;
    asm("{ .reg .u64 t; cvta.to.shared.u64 t, %1; cvt.u32.u64 %0, t; }":"=r"(a):"l"(p));
    return a;
}
__device__ __forceinline__ void cpa16(uint32_t dst, const void* src, int sz){
    asm volatile("cp.async.cg.shared.global [%0],[%1],16,%2;"
                 ::"r"(dst),"l"(src),"r"(sz):"memory");
}
__device__ __forceinline__ void mma16(float* c, const uint32_t* a, const uint32_t* b){
    asm volatile("mma.sync.aligned.m16n8k16.row.col.f32.f16.f16.f32 "
        "{%0,%1,%2,%3},{%4,%5,%6,%7},{%8,%9},{%0,%1,%2,%3};"
        :"+f"(c[0]),"+f"(c[1]),"+f"(c[2]),"+f"(c[3])
        :"r"(a[0]),"r"(a[1]),"r"(a[2]),"r"(a[3]),"r"(b[0]),"r"(b[1]));
}
#define LDSM4(r, a) \
    asm volatile("ldmatrix.sync.aligned.m8n8.x4.shared.b16 {%0,%1,%2,%3},[%4];" \
        :"=r"((r)[0]),"=r"((r)[1]),"=r"((r)[2]),"=r"((r)[3]):"r"(a))

// smem: 3 planes (Ah, Bh, Bl), 128 rows x 64 halves (128B) padded to 144B/row
#define KC 64
#define RSTR 144
#define PLANE (128*RSTR)          // 18432
#define BUFB (3*PLANE)            // 55296
#define DSM (2*BUFB)              // 110592

// MODE 0: plain. MODE 1: token-gather A (slot out). MODE 2: slot A -> weighted scatter.
// MODE 3: QKV fused. CTA 128x128, 256 thr, warps 2m x 4n, warp tile 64x32.
// 2-term: fp16 activations x exact weights (a*bh + a*bl).
template<int MODE>
__global__ __launch_bounds__(256) void hgemm(
    const __half* __restrict__ Ah,
    const __half* __restrict__ Bh, const __half* __restrict__ Bl,
    const float* __restrict__ bias, const float* __restrict__ res,
    const float* __restrict__ comp, float* __restrict__ Cf,
    __half* __restrict__ Ch,
    int N, int Kd, QKVH q3)
{
    extern __shared__ __align__(16) char sm[];
    const int tid = threadIdx.x, wid = tid>>5, lane = tid&31;
    const int warp_m = wid&1, warp_n = wid>>1;
    const int bm = blockIdx.y*128, bn = blockIdx.x*128;
    int count = 1<<30, base = 0;
    if (MODE == 1 || MODE == 2){
        int e = blockIdx.z;
        count = g_cnt[e]; base = g_off[e];
        if (bm >= count) return;
        Bh += (size_t)e*N*Kd; Bl += (size_t)e*N*Kd;
        bias += (size_t)e*N;
    }
    if (MODE == 3){
        int z = blockIdx.z;
        Bh = q3.bh[z]; Bl = q3.bl[z]; bias = q3.bias[z]; Cf = q3.c[z];
    }
    // A row pointers: 4 rows per thread (sr+32i)
    const int sr = tid>>3, sc8 = tid&7;
    const __half* pAh[4]; int avv[4];
#pragma unroll
    for (int i = 0; i < 4; i++){
        int row = bm + sr + 32*i;
        avv[i] = 16;
        if (MODE == 1){
            bool v = row < count;
            avv[i] = v ? 16 : 0;
            pAh[i] = Ah + (size_t)(v ? g_tok[base+row] : 0)*Kd;
        } else if (MODE == 2){
            pAh[i] = Ah + (size_t)(base + (row < count ? row : count-1))*Kd;
        } else {
            pAh[i] = Ah + (size_t)row*Kd;
        }
    }
    const uint32_t smu = smem_u32(sm);
    const uint32_t sdst = smu + (uint32_t)sr*RSTR + (uint32_t)sc8*16u;
    // ldmatrix lane bases
    const int mat = lane>>3, l7 = lane&7;
    const uint32_t a_lm = smu
        + (uint32_t)((warp_m*64 + (mat&1)*8 + l7)*RSTR + (mat>>1)*16);
    const uint32_t b_lm = smu + PLANE
        + (uint32_t)((warp_n*32 + (mat>>1)*8 + l7)*RSTR + (mat&1)*16);

    const int nch = Kd/KC;
    // prologue: chunk 0 -> buf 0
#pragma unroll
    for (int i = 0; i < 4; i++){
        uint32_t d = sdst + (uint32_t)(32*i)*RSTR;
        cpa16(d,            pAh[i] + sc8*8, avv[i]);
        cpa16(d + PLANE,    Bh + (size_t)(bn+sr+32*i)*Kd + sc8*8, 16);
        cpa16(d + 2*PLANE,  Bl + (size_t)(bn+sr+32*i)*Kd + sc8*8, 16);
    }
    asm volatile("cp.async.commit_group;":::"memory");

    float acc[4][4][4];
#pragma unroll
    for (int a = 0; a < 4; a++)
#pragma unroll
        for (int b = 0; b < 4; b++)
#pragma unroll
            for (int r = 0; r < 4; r++) acc[a][b][r] = 0.f;

    for (int c = 0; c < nch; c++){
        const uint32_t bufo = (uint32_t)(c&1)*BUFB;
        if (c+1 < nch){
            const uint32_t nb = (uint32_t)((c+1)&1)*BUFB;
            const int k0 = (c+1)*KC;
#pragma unroll
            for (int i = 0; i < 4; i++){
                uint32_t d = sdst + nb + (uint32_t)(32*i)*RSTR;
                cpa16(d,           pAh[i] + k0 + sc8*8, avv[i]);
                cpa16(d + PLANE,   Bh + (size_t)(bn+sr+32*i)*Kd + k0 + sc8*8, 16);
                cpa16(d + 2*PLANE, Bl + (size_t)(bn+sr+32*i)*Kd + k0 + sc8*8, 16);
            }
            asm volatile("cp.async.commit_group;":::"memory");
            asm volatile("cp.async.wait_group 1;":::"memory");
        } else {
            asm volatile("cp.async.wait_group 0;":::"memory");
        }
        __syncthreads();
#pragma unroll
        for (int ks = 0; ks < 4; ks++){
            uint32_t ah[4][4], bh4[2][4], bl4[2][4];
#pragma unroll
            for (int mf = 0; mf < 4; mf++)
                LDSM4(ah[mf], a_lm + bufo + mf*(16*RSTR) + ks*32);
#pragma unroll
            for (int np = 0; np < 2; np++){
                LDSM4(bh4[np], b_lm + bufo + np*(16*RSTR) + ks*32);
                LDSM4(bl4[np], b_lm + bufo + PLANE + np*(16*RSTR) + ks*32);
            }
            // term-grouped: 16 independent hh, then 16 hl
#pragma unroll
            for (int np = 0; np < 2; np++)
#pragma unroll
                for (int mf = 0; mf < 4; mf++)
#pragma unroll
                    for (int j = 0; j < 2; j++)
                        mma16(acc[mf][np*2+j], ah[mf], &bh4[np][j*2]);
#pragma unroll
            for (int np = 0; np < 2; np++)
#pragma unroll
                for (int mf = 0; mf < 4; mf++)
#pragma unroll
                    for (int j = 0; j < 2; j++)
                        mma16(acc[mf][np*2+j], ah[mf], &bl4[np][j*2]);
        }
        __syncthreads();
    }

    // epilogue
    const int qr = lane>>2, qc = lane&3;
#pragma unroll
    for (int mf = 0; mf < 4; mf++){
#pragma unroll
        for (int hf = 0; hf < 2; hf++){
            int rl = warp_m*64 + mf*16 + qr + hf*8;
            bool rv = true; size_t crow = (size_t)(bm + rl); float ws = 1.f;
            if (MODE == 1){ rv = (bm + rl) < count; crow = (size_t)(base + bm + rl); }
            if (MODE == 2){
                rv = (bm + rl) < count;
                int s2 = rv ? (base + bm + rl) : base;
                crow = (size_t)g_tok[s2]; ws = g_wa[s2];
            }
            if (!rv) continue;
#pragma unroll
            for (int nf = 0; nf < 4; nf++){
                int col = bn + warp_n*32 + nf*8 + qc*2;
                float v0 = acc[mf][nf][hf*2+0] + bias[col];
                float v1 = acc[mf][nf][hf*2+1] + bias[col+1];
                if (comp){
                    float c0 = comp[crow*N + col], c1 = comp[crow*N + col + 1];
                    v0 *= c0/(1.f+__expf(-c0));
                    v1 *= c1/(1.f+__expf(-c1));
                }
                if (MODE == 2){
                    atomicAdd(Cf + crow*N + col,     ws*v0);
                    atomicAdd(Cf + crow*N + col + 1, ws*v1);
                } else if (Ch){
                    __half2 h2 = __floats2half2_rn(v0, v1);
                    *(uint32_t*)(Ch + crow*N + col) = *reinterpret_cast<uint32_t*>(&h2);
                } else {
                    if (res){ v0 += res[crow*N + col]; v1 += res[crow*N + col + 1]; }
                    *(float2*)(Cf + crow*N + col) = make_float2(v0, v1);
                }
            }
        }
    }
}

// ---------------- weight transpose + split (hi + lo) -----------------------------
__global__ __launch_bounds__(256) void wsplitT(const float* __restrict__ in,
                                               __half* __restrict__ oh,
                                               __half* __restrict__ ol, int K, int N)
{
    __shared__ float s[32][33];
    size_t bo = (size_t)blockIdx.z * K * N;
    in += bo; oh += bo; ol += bo;
    int n0 = blockIdx.x*32, k0 = blockIdx.y*32;
    int tx = threadIdx.x & 31, ty = threadIdx.x >> 5;
#pragma unroll
    for (int i = 0; i < 4; i++)
        s[ty + 8*i][tx] = in[(size_t)(k0 + ty + 8*i)*N + n0 + tx];
    __syncthreads();
    int n = threadIdx.x >> 3, cc = threadIdx.x & 7;
    uint32_t hw[2], lw[2];
#pragma unroll
    for (int p = 0; p < 2; p++){
        float x0 = s[cc*4 + p*2 + 0][n], x1 = s[cc*4 + p*2 + 1][n];
        __half2 h2 = __floats2half2_rn(x0, x1);
        float2 hf = __half22float2(h2);
        __half2 l2 = __floats2half2_rn(x0 - hf.x, x1 - hf.y);
        hw[p] = *reinterpret_cast<uint32_t*>(&h2);
        lw[p] = *reinterpret_cast<uint32_t*>(&l2);
    }
    size_t o = (size_t)(n0 + n)*K + k0 + cc*4;
    *(uint2*)(oh + o) = make_uint2(hw[0], hw[1]);
    *(uint2*)(ol + o) = make_uint2(lw[0], lw[1]);
}

// ---------------- SIMT parts ----------------
__device__ __forceinline__ void mma_step(const float (*As)[64], const float (*Bs)[64],
                                         float acc[4][4], int ty4, int tx4)
{
#pragma unroll
    for (int kk = 0; kk < 16; kk++){
        float a[4], b[4];
#pragma unroll
        for (int i = 0; i < 4; i++) a[i] = As[kk][ty4+i];
#pragma unroll
        for (int j = 0; j < 4; j++) b[j] = Bs[kk][tx4+j];
#pragma unroll
        for (int i = 0; i < 4; i++)
#pragma unroll
            for (int j = 0; j < 4; j++) acc[i][j] = fmaf(a[i], b[j], acc[i][j]);
    }
}

__global__ __launch_bounds__(256) void ln_kernel(const float* __restrict__ x,
                                                 const float* __restrict__ g,
                                                 float* __restrict__ of,
                                                 __half* __restrict__ oh)
{
    __shared__ float red[256];
    const int row = blockIdx.x, t = threadIdx.x;
    const float* xr = x + (size_t)row*DM;
    float s = 0.f;
    for (int i = t; i < DM; i += 256) s += xr[i];
    red[t] = s; __syncthreads();
    for (int k = 128; k > 0; k >>= 1){ if (t < k) red[t] += red[t+k]; __syncthreads(); }
    const float mu = red[0]*(1.f/DM); __syncthreads();
    float v = 0.f;
    for (int i = t; i < DM; i += 256){ float d0 = xr[i]-mu; v += d0*d0; }
    red[t] = v; __syncthreads();
    for (int k = 128; k > 0; k >>= 1){ if (t < k) red[t] += red[t+k]; __syncthreads(); }
    const float inv = rsqrtf(red[0]*(1.f/DM) + 1e-8f);
    for (int i = t; i < DM; i += 256){
        float val = (xr[i]-mu)*inv*g[i];
        size_t o = (size_t)row*DM + i;
        if (of) of[o] = val;
        oh[o] = __float2half_rn(val);
    }
}

__global__ __launch_bounds__(256) void score_kernel(const float* __restrict__ mask)
{
    if (blockIdx.x > blockIdx.y) return;   // fully masked (causal)
    __shared__ float As[16][64];
    __shared__ float Bs[16][64];
    const int h = blockIdx.z, bi = blockIdx.y*64, bj = blockIdx.x*64;
    const int tid = threadIdx.x;
    const int tx4 = (tid&15)*4, ty4 = (tid>>4)*4;
    const int am = tid>>2, ak = (tid&3)*4;
    float acc[4][4] = {};
    const float* qp = g_q + (size_t)(bi+am)*HDIM + h*DKV + ak;
    const float* kp = g_k + (size_t)(bj+am)*HDIM + h*DKV + ak;
    for (int k0 = 0; k0 < DKV; k0 += 16){
        float4 a = *(const float4*)(qp+k0);
        As[ak+0][am]=a.x; As[ak+1][am]=a.y; As[ak+2][am]=a.z; As[ak+3][am]=a.w;
        float4 b = *(const float4*)(kp+k0);
        Bs[ak+0][am]=b.x; Bs[ak+1][am]=b.y; Bs[ak+2][am]=b.z; Bs[ak+3][am]=b.w;
        __syncthreads();
        mma_step(As, Bs, acc, ty4, tx4);
        __syncthreads();
    }
    const float slope = exp2f(-(float)(h+1));
    const float sc = 0.08838834764831845f;
#pragma unroll
    for (int i = 0; i < 4; i++){
        int gi = bi+ty4+i;
#pragma unroll
        for (int j = 0; j < 4; j++){
            int gj = bj+tx4+j;
            float al = (gi >= gj) ? -(float)(gi-gj)*slope : 0.f;
            g_sc[((size_t)h*SQ+gi)*SQ+gj] = acc[i][j]*sc + al + mask[(size_t)gi*SQ+gj];
        }
    }
}

__global__ __launch_bounds__(256) void softmax_kernel()
{
    __shared__ float red[256];
    float* r = g_sc + (size_t)blockIdx.x*SQ;
    const int i = blockIdx.x & (SQ-1);
    const int t = threadIdx.x;
    const int j0 = 4*t;
    float4 v = ((float4*)r)[t];
    float m0 = (j0+0 <= i) ? v.x : -1e30f;
    float m1 = (j0+1 <= i) ? v.y : -1e30f;
    float m2 = (j0+2 <= i) ? v.z : -1e30f;
    float m3 = (j0+3 <= i) ? v.w : -1e30f;
    float m = fmaxf(fmaxf(m0,m1), fmaxf(m2,m3));
    red[t] = m; __syncthreads();
    for (int k = 128; k > 0; k >>= 1){ if (t < k) red[t] = fmaxf(red[t], red[t+k]); __syncthreads(); }
    m = red[0]; __syncthreads();
    float4 e;
    e.x = (j0+0 <= i) ? __expf(v.x-m) : 0.f;
    e.y = (j0+1 <= i) ? __expf(v.y-m) : 0.f;
    e.z = (j0+2 <= i) ? __expf(v.z-m) : 0.f;
    e.w = (j0+3 <= i) ? __expf(v.w-m) : 0.f;
    red[t] = e.x+e.y+e.z+e.w; __syncthreads();
    for (int k = 128; k > 0; k >>= 1){ if (t < k) red[t] += red[t+k]; __syncthreads(); }
    const float inv = 1.f/red[0];
    e.x*=inv; e.y*=inv; e.z*=inv; e.w*=inv;
    ((float4*)r)[t] = e;
}

__global__ __launch_bounds__(256) void pv_kernel()
{
    __shared__ float As[16][64];
    __shared__ float Bs[16][64];
    const int h = blockIdx.z, bm = blockIdx.y*64, bn = blockIdx.x*64;
    const int tid = threadIdx.x;
    const int tx4 = (tid&15)*4, ty4 = (tid>>4)*4;
    const int bkr = tid>>4, bc = (tid&15)*4;
    float acc[4][4] = {};
    const float* Pp = g_sc + (size_t)h*SQ*SQ + (size_t)bkr*SQ + bm + bc;
    const float* Vp = g_v + (size_t)bkr*HDIM + h*DKV + bn + bc;
    for (int k0 = bm; k0 < SQ; k0 += 16){
        *(float4*)(&As[bkr][bc]) = *(const float4*)(Pp + (size_t)k0*SQ);
        *(float4*)(&Bs[bkr][bc]) = *(const float4*)(Vp + (size_t)k0*HDIM);
        __syncthreads();
        mma_step(As, Bs, acc, ty4, tx4);
        __syncthreads();
    }
#pragma unroll
    for (int i = 0; i < 4; i++){
        size_t rb = (size_t)(bm+ty4+i)*HDIM + h*DKV + bn + tx4;
#pragma unroll
        for (int j = 0; j < 4; j += 2){
            __half2 h2 = __floats2half2_rn(acc[i][j], acc[i][j+1]);
            *(uint32_t*)(a_at_h + rb + j) = *reinterpret_cast<uint32_t*>(&h2);
        }
    }
}

__global__ void reset_kernel(){
    int t = threadIdx.x;
    if (t < NE){ g_cnt[t] = 0; g_pos[t] = 0; }
}

__global__ __launch_bounds__(256) void gate_kernel(const float* __restrict__ xf,
                                                   const float* __restrict__ gw,
                                                   const float* __restrict__ gb)
{
    __shared__ float xs[DM];
    __shared__ float lg[NE];
    const int tok = blockIdx.x, tid = threadIdx.x;
    for (int i = tid; i < DM; i += 256) xs[i] = xf[(size_t)tok*DM+i];
    __syncthreads();
    const int warp = tid>>5, lane = tid&31;
    for (int e = warp; e < NE; e += 8){
        const float* w = gw + (size_t)e*DM;
        float s = 0.f;
        for (int i = lane; i < DM; i += 32) s += xs[i]*w[i];
        for (int o = 16; o; o >>= 1) s += __shfl_down_sync(0xFFFFFFFFu, s, o);
        if (lane == 0) lg[e] = s;
    }
    __syncthreads();
    if (tid == 0){
        float mx = -1e30f;
        for (int e = 0; e < NE; e++) mx = fmaxf(mx, lg[e]);
        float sm[NE], se = 0.f;
        for (int e = 0; e < NE; e++){ sm[e] = expf(lg[e]-mx); se += sm[e]; }
        float inv = 1.f/se;
        for (int e = 0; e < NE; e++) sm[e] *= inv;
        bool used[NE] = {};
        for (int kk = 0; kk < TOPK; kk++){
            float best = -1e30f; int bi = 0;
            for (int e = 0; e < NE; e++)
                if (!used[e]){ float s = sm[e]+gb[e]; if (s > best){ best = s; bi = e; } }
            used[bi] = true;
            g_idx[tok*TOPK+kk] = bi;
            g_wt[tok*TOPK+kk] = sm[bi];
            atomicAdd(&g_cnt[bi], 1);
        }
    }
}

// merged scan + place (single block)
__global__ __launch_bounds__(256) void scanplace_kernel(){
    __shared__ int off_s[NE];
    if (threadIdx.x == 0){
        int r = 0;
        for (int e = 0; e < NE; e++){ off_s[e] = r; g_off[e] = r; r += g_cnt[e]; }
    }
    __syncthreads();
    for (int t = threadIdx.x; t < SQ; t += 256){
        for (int kk = 0; kk < TOPK; kk++){
            int e = g_idx[t*TOPK+kk];
            int p = off_s[e] + atomicAdd(&g_pos[e], 1);
            g_tok[p] = t;
            g_wa[p] = g_wt[t*TOPK+kk];
        }
    }
}

#define SYM(var, name) cudaGetSymbolAddress((void**)&var, name)

extern "C" void kernel_launch(void* const* d_in, const int* in_sizes, int n_in,
                              void* d_out, int out_size)
{
    const float* x      = (const float*)d_in[0];
    const float* mask   = (const float*)d_in[1];
    const float* attn_g = (const float*)d_in[2];
    const float* wq_w   = (const float*)d_in[3];
    const float* wq_b   = (const float*)d_in[4];
    const float* wk_w   = (const float*)d_in[5];
    const float* wk_b   = (const float*)d_in[6];
    const float* wv_w   = (const float*)d_in[7];
    const float* wv_b   = (const float*)d_in[8];
    const float* wo_w   = (const float*)d_in[9];
    const float* wo_b   = (const float*)d_in[10];
    const float* ffn_g  = (const float*)d_in[11];
    const float* gate_w = (const float*)d_in[12];
    const float* gate_b = (const float*)d_in[13];
    const float* e_w1   = (const float*)d_in[14];
    const float* e_b1   = (const float*)d_in[15];
    const float* e_w2   = (const float*)d_in[16];
    const float* e_b2   = (const float*)d_in[17];
    const float* e_w3   = (const float*)d_in[18];
    const float* e_b3   = (const float*)d_in[19];
    const float* s_w1   = (const float*)d_in[20];
    const float* s_b1   = (const float*)d_in[21];
    const float* s_w2   = (const float*)d_in[22];
    const float* s_b2   = (const float*)d_in[23];
    const float* s_w3   = (const float*)d_in[24];
    const float* s_b3   = (const float*)d_in[25];
    float* outp = (float*)d_out;

    float *p_q,*p_k,*p_v,*p_x2,*p_ln2,*p_t1,*p_h1;
    SYM(p_q, g_q); SYM(p_k, g_k); SYM(p_v, g_v);
    SYM(p_x2, g_x2); SYM(p_ln2, g_ln2); SYM(p_t1, g_t1); SYM(p_h1, g_h1);
    __half *lnH,*atH,*l2H,*hsH,*hhH;
    SYM(lnH, a_ln_h); SYM(atH, a_at_h); SYM(l2H, a_l2_h);
    SYM(hsH, a_hs_h); SYM(hhH, a_hh_h);
    __half *wqH,*wqL,*wkH,*wkL,*wvH,*wvL,*woH,*woL;
    __half *s1H,*s1L,*s3H,*s3L,*s2H,*s2L,*e1H,*e1L,*e3H,*e3L,*e2H,*e2L;
    SYM(wqH, w_q_h); SYM(wqL, w_q_l); SYM(wkH, w_k_h); SYM(wkL, w_k_l);
    SYM(wvH, w_v_h); SYM(wvL, w_v_l); SYM(woH, w_o_h); SYM(woL, w_o_l);
    SYM(s1H, w_s1_h); SYM(s1L, w_s1_l); SYM(s3H, w_s3_h); SYM(s3L, w_s3_l);
    SYM(s2H, w_s2_h); SYM(s2L, w_s2_l);
    SYM(e1H, w_e1_h); SYM(e1L, w_e1_l); SYM(e3H, w_e3_h); SYM(e3L, w_e3_l);
    SYM(e2H, w_e2_h); SYM(e2L, w_e2_l);

    cudaFuncSetAttribute(hgemm<0>, cudaFuncAttributeMaxDynamicSharedMemorySize, DSM);
    cudaFuncSetAttribute(hgemm<1>, cudaFuncAttributeMaxDynamicSharedMemorySize, DSM);
    cudaFuncSetAttribute(hgemm<2>, cudaFuncAttributeMaxDynamicSharedMemorySize, DSM);
    cudaFuncSetAttribute(hgemm<3>, cudaFuncAttributeMaxDynamicSharedMemorySize, DSM);

    // side stream for big weight splits (overlaps attention phase)
    static cudaStream_t s1 = nullptr;
    static cudaEvent_t ev0 = nullptr, ev1 = nullptr;
    if (!s1){
        cudaStreamCreateWithFlags(&s1, cudaStreamNonBlocking);
        cudaEventCreateWithFlags(&ev0, cudaEventDisableTiming);
        cudaEventCreateWithFlags(&ev1, cudaEventDisableTiming);
    }
    cudaEventRecord(ev0, 0);
    cudaStreamWaitEvent(s1, ev0, 0);
    wsplitT<<<dim3(FSH/32, DM/32, 1), 256, 0, s1>>>(s_w1, s1H, s1L, DM, FSH);
    wsplitT<<<dim3(FSH/32, DM/32, 1), 256, 0, s1>>>(s_w3, s3H, s3L, DM, FSH);
    wsplitT<<<dim3(DM/32, FSH/32, 1), 256, 0, s1>>>(s_w2, s2H, s2L, FSH, DM);
    wsplitT<<<dim3(FF/32, DM/32, NE), 256, 0, s1>>>(e_w1, e1H, e1L, DM, FF);
    wsplitT<<<dim3(FF/32, DM/32, NE), 256, 0, s1>>>(e_w3, e3H, e3L, DM, FF);
    wsplitT<<<dim3(DM/32, FF/32, NE), 256, 0, s1>>>(e_w2, e2H, e2L, FF, DM);
    cudaEventRecord(ev1, s1);

    // attention-path splits on main stream
    wsplitT<<<dim3(HDIM/32, DM/32, 1), 256>>>(wq_w, wqH, wqL, DM, HDIM);
    wsplitT<<<dim3(HDIM/32, DM/32, 1), 256>>>(wk_w, wkH, wkL, DM, HDIM);
    wsplitT<<<dim3(HDIM/32, DM/32, 1), 256>>>(wv_w, wvH, wvL, DM, HDIM);
    wsplitT<<<dim3(DM/32, HDIM/32, 1), 256>>>(wo_w, woH, woL, HDIM, DM);

    QKVH z3 = {};
    QKVH qkv;
    qkv.bh[0]=wqH; qkv.bh[1]=wkH; qkv.bh[2]=wvH;
    qkv.bl[0]=wqL; qkv.bl[1]=wkL; qkv.bl[2]=wvL;
    qkv.bias[0]=wq_b; qkv.bias[1]=wk_b; qkv.bias[2]=wv_b;
    qkv.c[0]=p_q; qkv.c[1]=p_k; qkv.c[2]=p_v;

    // ---- attention ----
    ln_kernel<<<SQ, 256>>>(x, attn_g, nullptr, lnH);
    hgemm<3><<<dim3(HDIM/128, SQ/128, 3), 256, DSM>>>(lnH, nullptr, nullptr,
        nullptr, nullptr, nullptr, nullptr, nullptr, HDIM, DM, qkv);
    score_kernel<<<dim3(SQ/64, SQ/64, NH), 256>>>(mask);
    softmax_kernel<<<NH*SQ, 256>>>();
    pv_kernel<<<dim3(DKV/64, SQ/64, NH), 256>>>();
    hgemm<0><<<dim3(DM/128, SQ/128), 256, DSM>>>(atH, woH, woL,
        wo_b, x, nullptr, p_x2, nullptr, DM, HDIM, z3);

    // ---- moe routing ----
    ln_kernel<<<SQ, 256>>>(p_x2, ffn_g, p_ln2, l2H);
    reset_kernel<<<1, 32>>>();
    gate_kernel<<<SQ, 256>>>(p_ln2, gate_w, gate_b);
    scanplace_kernel<<<1, 256>>>();

    // join side-stream splits before MoE GEMMs
    cudaStreamWaitEvent(0, ev1, 0);

    // ---- shared expert ----
    hgemm<0><<<dim3(FSH/128, SQ/128), 256, DSM>>>(l2H, s1H, s1L,
        s_b1, nullptr, nullptr, p_t1, nullptr, FSH, DM, z3);
    hgemm<0><<<dim3(FSH/128, SQ/128), 256, DSM>>>(l2H, s3H, s3L,
        s_b3, nullptr, p_t1, nullptr, hsH, FSH, DM, z3);
    hgemm<0><<<dim3(DM/128, SQ/128), 256, DSM>>>(hsH, s2H, s2L,
        s_b2, p_x2, nullptr, outp, nullptr, DM, FSH, z3);

    // ---- routed experts ----
    hgemm<1><<<dim3(FF/128, SQ/128, NE), 256, DSM>>>(l2H, e1H, e1L,
        e_b1, nullptr, nullptr, p_h1, nullptr, FF, DM, z3);
    hgemm<1><<<dim3(FF/128, SQ/128, NE), 256, DSM>>>(l2H, e3H, e3L,
        e_b3, nullptr, p_h1, nullptr, hhH, FF, DM, z3);
    hgemm<2><<<dim3(DM/128, SQ/128, NE), 256, DSM>>>(hhH, e2H, e2L,
        e_b2, nullptr, nullptr, outp, nullptr, DM, FF, z3);
}

// round 17
// speedup vs baseline: 1.1274x; 1.0433x over previous
#include <cuda_runtime.h>
#include <cuda_fp16.h>
#include <cstdint>
#include <math.h>

#define SQ 1024
#define DM 2048
#define NH 8
#define DKV 128
#define HDIM 1024
#define NE 16
#define TOPK 6
#define FF 1408
#define FSH 2816
#define NSLOT (SQ*TOPK)

// fp32 scratch
__device__ float g_q[SQ*HDIM];
__device__ float g_k[SQ*HDIM];
__device__ float g_v[SQ*HDIM];
__device__ float g_sc[NH*SQ*SQ];
__device__ float g_x2[SQ*DM];
__device__ float g_ln2[SQ*DM];
__device__ float g_t1[SQ*FSH];
__device__ float g_h1[NSLOT*FF];
// half planes: activations (hi only)
__device__ __half a_ln_h[SQ*DM];
__device__ __half a_at_h[SQ*HDIM];
__device__ __half a_l2_h[SQ*DM];
__device__ __half a_hs_h[SQ*FSH];
__device__ __half a_hh_h[NSLOT*FF];
// half planes: weights transposed to [N][K], hi + lo (exact-weight 2-term)
__device__ __half w_q_h[HDIM*DM];  __device__ __half w_q_l[HDIM*DM];
__device__ __half w_k_h[HDIM*DM];  __device__ __half w_k_l[HDIM*DM];
__device__ __half w_v_h[HDIM*DM];  __device__ __half w_v_l[HDIM*DM];
__device__ __half w_o_h[DM*HDIM];  __device__ __half w_o_l[DM*HDIM];
__device__ __half w_s1_h[FSH*DM];  __device__ __half w_s1_l[FSH*DM];
__device__ __half w_s3_h[FSH*DM];  __device__ __half w_s3_l[FSH*DM];
__device__ __half w_s2_h[DM*FSH];  __device__ __half w_s2_l[DM*FSH];
__device__ __half w_e1_h[NE*FF*DM];__device__ __half w_e1_l[NE*FF*DM];
__device__ __half w_e3_h[NE*FF*DM];__device__ __half w_e3_l[NE*FF*DM];
__device__ __half w_e2_h[NE*DM*FF];__device__ __half w_e2_l[NE*DM*FF];
// routing
__device__ int   g_idx[SQ*TOPK];
__device__ float g_wt[SQ*TOPK];
__device__ int   g_cnt[NE];
__device__ int   g_off[NE];
__device__ int   g_pos[NE];
__device__ int   g_tok[NSLOT];
__device__ float g_wa[NSLOT];

struct QKVH { const __half* bh[3]; const __half* bl[3]; const float* bias[3]; float* c[3]; };

__device__ __forceinline__ uint32_t smem_u32(const void* p){
    uint32_t a;
    asm("{ .reg .u64 t; cvta.to.shared.u64 t, %1; cvt.u32.u64 %0, t; }":"=r"(a):"l"(p));
    return a;
}
__device__ __forceinline__ void cpa16(uint32_t dst, const void* src, int sz){
    asm volatile("cp.async.cg.shared.global [%0],[%1],16,%2;"
                 ::"r"(dst),"l"(src),"r"(sz):"memory");
}
__device__ __forceinline__ void mma16(float* c, const uint32_t* a, const uint32_t* b){
    asm volatile("mma.sync.aligned.m16n8k16.row.col.f32.f16.f16.f32 "
        "{%0,%1,%2,%3},{%4,%5,%6,%7},{%8,%9},{%0,%1,%2,%3};"
        :"+f"(c[0]),"+f"(c[1]),"+f"(c[2]),"+f"(c[3])
        :"r"(a[0]),"r"(a[1]),"r"(a[2]),"r"(a[3]),"r"(b[0]),"r"(b[1]));
}
#define LDSM4(r, a) \
    asm volatile("ldmatrix.sync.aligned.m8n8.x4.shared.b16 {%0,%1,%2,%3},[%4];" \
        :"=r"((r)[0]),"=r"((r)[1]),"=r"((r)[2]),"=r"((r)[3]):"r"(a))

// smem: 3 planes (Ah, Bh, Bl), 128 rows x 64 halves (128B) padded to 144B/row
#define KC 64
#define RSTR 144
#define PLANE (128*RSTR)          // 18432
#define BUFB (3*PLANE)            // 55296
#define DSM (2*BUFB)              // 110592

// MODE 0: plain. MODE 1: token-gather A (slot out). MODE 2: slot A -> weighted scatter.
// MODE 3: QKV fused. CTA 128x128, 256 thr, warps 2m x 4n, warp tile 64x32.
// 2-term: fp16 activations x exact weights (a*bh + a*bl).
template<int MODE>
__global__ __launch_bounds__(256) void hgemm(
    const __half* __restrict__ Ah,
    const __half* __restrict__ Bh, const __half* __restrict__ Bl,
    const float* __restrict__ bias, const float* __restrict__ res,
    const float* __restrict__ comp, float* __restrict__ Cf,
    __half* __restrict__ Ch,
    int N, int Kd, QKVH q3)
{
    extern __shared__ __align__(16) char sm[];
    const int tid = threadIdx.x, wid = tid>>5, lane = tid&31;
    const int warp_m = wid&1, warp_n = wid>>1;
    const int bm = blockIdx.y*128, bn = blockIdx.x*128;
    int count = 1<<30, base = 0;
    if (MODE == 1 || MODE == 2){
        int e = blockIdx.z;
        count = g_cnt[e]; base = g_off[e];
        if (bm >= count) return;
        Bh += (size_t)e*N*Kd; Bl += (size_t)e*N*Kd;
        bias += (size_t)e*N;
    }
    if (MODE == 3){
        int z = blockIdx.z;
        Bh = q3.bh[z]; Bl = q3.bl[z]; bias = q3.bias[z]; Cf = q3.c[z];
    }
    // A row pointers: 4 rows per thread (sr+32i)
    const int sr = tid>>3, sc8 = tid&7;
    const __half* pAh[4]; int avv[4];
#pragma unroll
    for (int i = 0; i < 4; i++){
        int row = bm + sr + 32*i;
        avv[i] = 16;
        if (MODE == 1){
            bool v = row < count;
            avv[i] = v ? 16 : 0;
            pAh[i] = Ah + (size_t)(v ? g_tok[base+row] : 0)*Kd;
        } else if (MODE == 2){
            pAh[i] = Ah + (size_t)(base + (row < count ? row : count-1))*Kd;
        } else {
            pAh[i] = Ah + (size_t)row*Kd;
        }
    }
    const uint32_t smu = smem_u32(sm);
    const uint32_t sdst = smu + (uint32_t)sr*RSTR + (uint32_t)sc8*16u;
    // ldmatrix lane bases
    const int mat = lane>>3, l7 = lane&7;
    const uint32_t a_lm = smu
        + (uint32_t)((warp_m*64 + (mat&1)*8 + l7)*RSTR + (mat>>1)*16);
    const uint32_t b_lm = smu + PLANE
        + (uint32_t)((warp_n*32 + (mat>>1)*8 + l7)*RSTR + (mat&1)*16);

    const int nch = Kd/KC;
    // prologue: chunk 0 -> buf 0
#pragma unroll
    for (int i = 0; i < 4; i++){
        uint32_t d = sdst + (uint32_t)(32*i)*RSTR;
        cpa16(d,            pAh[i] + sc8*8, avv[i]);
        cpa16(d + PLANE,    Bh + (size_t)(bn+sr+32*i)*Kd + sc8*8, 16);
        cpa16(d + 2*PLANE,  Bl + (size_t)(bn+sr+32*i)*Kd + sc8*8, 16);
    }
    asm volatile("cp.async.commit_group;":::"memory");

    float acc[4][4][4];
#pragma unroll
    for (int a = 0; a < 4; a++)
#pragma unroll
        for (int b = 0; b < 4; b++)
#pragma unroll
            for (int r = 0; r < 4; r++) acc[a][b][r] = 0.f;

    for (int c = 0; c < nch; c++){
        const uint32_t bufo = (uint32_t)(c&1)*BUFB;
        if (c+1 < nch){
            const uint32_t nb = (uint32_t)((c+1)&1)*BUFB;
            const int k0 = (c+1)*KC;
#pragma unroll
            for (int i = 0; i < 4; i++){
                uint32_t d = sdst + nb + (uint32_t)(32*i)*RSTR;
                cpa16(d,           pAh[i] + k0 + sc8*8, avv[i]);
                cpa16(d + PLANE,   Bh + (size_t)(bn+sr+32*i)*Kd + k0 + sc8*8, 16);
                cpa16(d + 2*PLANE, Bl + (size_t)(bn+sr+32*i)*Kd + k0 + sc8*8, 16);
            }
            asm volatile("cp.async.commit_group;":::"memory");
            asm volatile("cp.async.wait_group 1;":::"memory");
        } else {
            asm volatile("cp.async.wait_group 0;":::"memory");
        }
        __syncthreads();
#pragma unroll
        for (int ks = 0; ks < 4; ks++){
            uint32_t ah[4][4], bh4[2][4], bl4[2][4];
#pragma unroll
            for (int mf = 0; mf < 4; mf++)
                LDSM4(ah[mf], a_lm + bufo + mf*(16*RSTR) + ks*32);
#pragma unroll
            for (int np = 0; np < 2; np++){
                LDSM4(bh4[np], b_lm + bufo + np*(16*RSTR) + ks*32);
                LDSM4(bl4[np], b_lm + bufo + PLANE + np*(16*RSTR) + ks*32);
            }
            // term-grouped: 16 independent hh, then 16 hl
#pragma unroll
            for (int np = 0; np < 2; np++)
#pragma unroll
                for (int mf = 0; mf < 4; mf++)
#pragma unroll
                    for (int j = 0; j < 2; j++)
                        mma16(acc[mf][np*2+j], ah[mf], &bh4[np][j*2]);
#pragma unroll
            for (int np = 0; np < 2; np++)
#pragma unroll
                for (int mf = 0; mf < 4; mf++)
#pragma unroll
                    for (int j = 0; j < 2; j++)
                        mma16(acc[mf][np*2+j], ah[mf], &bl4[np][j*2]);
        }
        __syncthreads();
    }

    // epilogue
    const int qr = lane>>2, qc = lane&3;
#pragma unroll
    for (int mf = 0; mf < 4; mf++){
#pragma unroll
        for (int hf = 0; hf < 2; hf++){
            int rl = warp_m*64 + mf*16 + qr + hf*8;
            bool rv = true; size_t crow = (size_t)(bm + rl); float ws = 1.f;
            if (MODE == 1){ rv = (bm + rl) < count; crow = (size_t)(base + bm + rl); }
            if (MODE == 2){
                rv = (bm + rl) < count;
                int s2 = rv ? (base + bm + rl) : base;
                crow = (size_t)g_tok[s2]; ws = g_wa[s2];
            }
            if (!rv) continue;
#pragma unroll
            for (int nf = 0; nf < 4; nf++){
                int col = bn + warp_n*32 + nf*8 + qc*2;
                float v0 = acc[mf][nf][hf*2+0] + bias[col];
                float v1 = acc[mf][nf][hf*2+1] + bias[col+1];
                if (comp){
                    float c0 = comp[crow*N + col], c1 = comp[crow*N + col + 1];
                    v0 *= c0/(1.f+__expf(-c0));
                    v1 *= c1/(1.f+__expf(-c1));
                }
                if (MODE == 2){
                    atomicAdd(Cf + crow*N + col,     ws*v0);
                    atomicAdd(Cf + crow*N + col + 1, ws*v1);
                } else if (Ch){
                    __half2 h2 = __floats2half2_rn(v0, v1);
                    *(uint32_t*)(Ch + crow*N + col) = *reinterpret_cast<uint32_t*>(&h2);
                } else {
                    if (res){ v0 += res[crow*N + col]; v1 += res[crow*N + col + 1]; }
                    *(float2*)(Cf + crow*N + col) = make_float2(v0, v1);
                }
            }
        }
    }
}

// ---------------- weight transpose + split (hi + lo) -----------------------------
__global__ __launch_bounds__(256) void wsplitT(const float* __restrict__ in,
                                               __half* __restrict__ oh,
                                               __half* __restrict__ ol, int K, int N)
{
    __shared__ float s[32][33];
    size_t bo = (size_t)blockIdx.z * K * N;
    in += bo; oh += bo; ol += bo;
    int n0 = blockIdx.x*32, k0 = blockIdx.y*32;
    int tx = threadIdx.x & 31, ty = threadIdx.x >> 5;
#pragma unroll
    for (int i = 0; i < 4; i++)
        s[ty + 8*i][tx] = in[(size_t)(k0 + ty + 8*i)*N + n0 + tx];
    __syncthreads();
    int n = threadIdx.x >> 3, cc = threadIdx.x & 7;
    uint32_t hw[2], lw[2];
#pragma unroll
    for (int p = 0; p < 2; p++){
        float x0 = s[cc*4 + p*2 + 0][n], x1 = s[cc*4 + p*2 + 1][n];
        __half2 h2 = __floats2half2_rn(x0, x1);
        float2 hf = __half22float2(h2);
        __half2 l2 = __floats2half2_rn(x0 - hf.x, x1 - hf.y);
        hw[p] = *reinterpret_cast<uint32_t*>(&h2);
        lw[p] = *reinterpret_cast<uint32_t*>(&l2);
    }
    size_t o = (size_t)(n0 + n)*K + k0 + cc*4;
    *(uint2*)(oh + o) = make_uint2(hw[0], hw[1]);
    *(uint2*)(ol + o) = make_uint2(lw[0], lw[1]);
}

// ---------------- SIMT parts ----------------
__device__ __forceinline__ void mma_step(const float (*As)[64], const float (*Bs)[64],
                                         float acc[4][4], int ty4, int tx4)
{
#pragma unroll
    for (int kk = 0; kk < 16; kk++){
        float a[4], b[4];
#pragma unroll
        for (int i = 0; i < 4; i++) a[i] = As[kk][ty4+i];
#pragma unroll
        for (int j = 0; j < 4; j++) b[j] = Bs[kk][tx4+j];
#pragma unroll
        for (int i = 0; i < 4; i++)
#pragma unroll
            for (int j = 0; j < 4; j++) acc[i][j] = fmaf(a[i], b[j], acc[i][j]);
    }
}

__global__ __launch_bounds__(256) void ln_kernel(const float* __restrict__ x,
                                                 const float* __restrict__ g,
                                                 float* __restrict__ of,
                                                 __half* __restrict__ oh)
{
    __shared__ float red[256];
    const int row = blockIdx.x, t = threadIdx.x;
    const float* xr = x + (size_t)row*DM;
    float s = 0.f;
    for (int i = t; i < DM; i += 256) s += xr[i];
    red[t] = s; __syncthreads();
    for (int k = 128; k > 0; k >>= 1){ if (t < k) red[t] += red[t+k]; __syncthreads(); }
    const float mu = red[0]*(1.f/DM); __syncthreads();
    float v = 0.f;
    for (int i = t; i < DM; i += 256){ float d0 = xr[i]-mu; v += d0*d0; }
    red[t] = v; __syncthreads();
    for (int k = 128; k > 0; k >>= 1){ if (t < k) red[t] += red[t+k]; __syncthreads(); }
    const float inv = rsqrtf(red[0]*(1.f/DM) + 1e-8f);
    for (int i = t; i < DM; i += 256){
        float val = (xr[i]-mu)*inv*g[i];
        size_t o = (size_t)row*DM + i;
        if (of) of[o] = val;
        oh[o] = __float2half_rn(val);
    }
}

__global__ __launch_bounds__(256) void score_kernel(const float* __restrict__ mask)
{
    if (blockIdx.x > blockIdx.y) return;   // fully masked (causal)
    __shared__ float As[16][64];
    __shared__ float Bs[16][64];
    const int h = blockIdx.z, bi = blockIdx.y*64, bj = blockIdx.x*64;
    const int tid = threadIdx.x;
    const int tx4 = (tid&15)*4, ty4 = (tid>>4)*4;
    const int am = tid>>2, ak = (tid&3)*4;
    float acc[4][4] = {};
    const float* qp = g_q + (size_t)(bi+am)*HDIM + h*DKV + ak;
    const float* kp = g_k + (size_t)(bj+am)*HDIM + h*DKV + ak;
    for (int k0 = 0; k0 < DKV; k0 += 16){
        float4 a = *(const float4*)(qp+k0);
        As[ak+0][am]=a.x; As[ak+1][am]=a.y; As[ak+2][am]=a.z; As[ak+3][am]=a.w;
        float4 b = *(const float4*)(kp+k0);
        Bs[ak+0][am]=b.x; Bs[ak+1][am]=b.y; Bs[ak+2][am]=b.z; Bs[ak+3][am]=b.w;
        __syncthreads();
        mma_step(As, Bs, acc, ty4, tx4);
        __syncthreads();
    }
    const float slope = exp2f(-(float)(h+1));
    const float sc = 0.08838834764831845f;
#pragma unroll
    for (int i = 0; i < 4; i++){
        int gi = bi+ty4+i;
#pragma unroll
        for (int j = 0; j < 4; j++){
            int gj = bj+tx4+j;
            float al = (gi >= gj) ? -(float)(gi-gj)*slope : 0.f;
            g_sc[((size_t)h*SQ+gi)*SQ+gj] = acc[i][j]*sc + al + mask[(size_t)gi*SQ+gj];
        }
    }
}

__global__ __launch_bounds__(256) void softmax_kernel()
{
    __shared__ float red[256];
    float* r = g_sc + (size_t)blockIdx.x*SQ;
    const int i = blockIdx.x & (SQ-1);
    const int t = threadIdx.x;
    const int j0 = 4*t;
    float4 v = ((float4*)r)[t];
    float m0 = (j0+0 <= i) ? v.x : -1e30f;
    float m1 = (j0+1 <= i) ? v.y : -1e30f;
    float m2 = (j0+2 <= i) ? v.z : -1e30f;
    float m3 = (j0+3 <= i) ? v.w : -1e30f;
    float m = fmaxf(fmaxf(m0,m1), fmaxf(m2,m3));
    red[t] = m; __syncthreads();
    for (int k = 128; k > 0; k >>= 1){ if (t < k) red[t] = fmaxf(red[t], red[t+k]); __syncthreads(); }
    m = red[0]; __syncthreads();
    float4 e;
    e.x = (j0+0 <= i) ? __expf(v.x-m) : 0.f;
    e.y = (j0+1 <= i) ? __expf(v.y-m) : 0.f;
    e.z = (j0+2 <= i) ? __expf(v.z-m) : 0.f;
    e.w = (j0+3 <= i) ? __expf(v.w-m) : 0.f;
    red[t] = e.x+e.y+e.z+e.w; __syncthreads();
    for (int k = 128; k > 0; k >>= 1){ if (t < k) red[t] += red[t+k]; __syncthreads(); }
    const float inv = 1.f/red[0];
    e.x*=inv; e.y*=inv; e.z*=inv; e.w*=inv;
    ((float4*)r)[t] = e;
}

__global__ __launch_bounds__(256) void pv_kernel()
{
    __shared__ float As[16][64];
    __shared__ float Bs[16][64];
    const int h = blockIdx.z, bm = blockIdx.y*64, bn = blockIdx.x*64;
    const int tid = threadIdx.x;
    const int tx4 = (tid&15)*4, ty4 = (tid>>4)*4;
    const int bkr = tid>>4, bc = (tid&15)*4;
    float acc[4][4] = {};
    const float* Pp = g_sc + (size_t)h*SQ*SQ + (size_t)bkr*SQ + bm + bc;
    const float* Vp = g_v + (size_t)bkr*HDIM + h*DKV + bn + bc;
    for (int k0 = bm; k0 < SQ; k0 += 16){
        *(float4*)(&As[bkr][bc]) = *(const float4*)(Pp + (size_t)k0*SQ);
        *(float4*)(&Bs[bkr][bc]) = *(const float4*)(Vp + (size_t)k0*HDIM);
        __syncthreads();
        mma_step(As, Bs, acc, ty4, tx4);
        __syncthreads();
    }
#pragma unroll
    for (int i = 0; i < 4; i++){
        size_t rb = (size_t)(bm+ty4+i)*HDIM + h*DKV + bn + tx4;
#pragma unroll
        for (int j = 0; j < 4; j += 2){
            __half2 h2 = __floats2half2_rn(acc[i][j], acc[i][j+1]);
            *(uint32_t*)(a_at_h + rb + j) = *reinterpret_cast<uint32_t*>(&h2);
        }
    }
}

__global__ void reset_kernel(){
    int t = threadIdx.x;
    if (t < NE){ g_cnt[t] = 0; g_pos[t] = 0; }
}

__global__ __launch_bounds__(256) void gate_kernel(const float* __restrict__ xf,
                                                   const float* __restrict__ gw,
                                                   const float* __restrict__ gb)
{
    __shared__ float xs[DM];
    __shared__ float lg[NE];
    const int tok = blockIdx.x, tid = threadIdx.x;
    for (int i = tid; i < DM; i += 256) xs[i] = xf[(size_t)tok*DM+i];
    __syncthreads();
    const int warp = tid>>5, lane = tid&31;
    for (int e = warp; e < NE; e += 8){
        const float* w = gw + (size_t)e*DM;
        float s = 0.f;
        for (int i = lane; i < DM; i += 32) s += xs[i]*w[i];
        for (int o = 16; o; o >>= 1) s += __shfl_down_sync(0xFFFFFFFFu, s, o);
        if (lane == 0) lg[e] = s;
    }
    __syncthreads();
    if (tid == 0){
        float mx = -1e30f;
        for (int e = 0; e < NE; e++) mx = fmaxf(mx, lg[e]);
        float sm[NE], se = 0.f;
        for (int e = 0; e < NE; e++){ sm[e] = expf(lg[e]-mx); se += sm[e]; }
        float inv = 1.f/se;
        for (int e = 0; e < NE; e++) sm[e] *= inv;
        bool used[NE] = {};
        for (int kk = 0; kk < TOPK; kk++){
            float best = -1e30f; int bi = 0;
            for (int e = 0; e < NE; e++)
                if (!used[e]){ float s = sm[e]+gb[e]; if (s > best){ best = s; bi = e; } }
            used[bi] = true;
            g_idx[tok*TOPK+kk] = bi;
            g_wt[tok*TOPK+kk] = sm[bi];
            atomicAdd(&g_cnt[bi], 1);
        }
    }
}

// merged scan + place (single block)
__global__ __launch_bounds__(256) void scanplace_kernel(){
    __shared__ int off_s[NE];
    if (threadIdx.x == 0){
        int r = 0;
        for (int e = 0; e < NE; e++){ off_s[e] = r; g_off[e] = r; r += g_cnt[e]; }
    }
    __syncthreads();
    for (int t = threadIdx.x; t < SQ; t += 256){
        for (int kk = 0; kk < TOPK; kk++){
            int e = g_idx[t*TOPK+kk];
            int p = off_s[e] + atomicAdd(&g_pos[e], 1);
            g_tok[p] = t;
            g_wa[p] = g_wt[t*TOPK+kk];
        }
    }
}

#define SYM(var, name) cudaGetSymbolAddress((void**)&var, name)

extern "C" void kernel_launch(void* const* d_in, const int* in_sizes, int n_in,
                              void* d_out, int out_size)
{
    const float* x      = (const float*)d_in[0];
    const float* mask   = (const float*)d_in[1];
    const float* attn_g = (const float*)d_in[2];
    const float* wq_w   = (const float*)d_in[3];
    const float* wq_b   = (const float*)d_in[4];
    const float* wk_w   = (const float*)d_in[5];
    const float* wk_b   = (const float*)d_in[6];
    const float* wv_w   = (const float*)d_in[7];
    const float* wv_b   = (const float*)d_in[8];
    const float* wo_w   = (const float*)d_in[9];
    const float* wo_b   = (const float*)d_in[10];
    const float* ffn_g  = (const float*)d_in[11];
    const float* gate_w = (const float*)d_in[12];
    const float* gate_b = (const float*)d_in[13];
    const float* e_w1   = (const float*)d_in[14];
    const float* e_b1   = (const float*)d_in[15];
    const float* e_w2   = (const float*)d_in[16];
    const float* e_b2   = (const float*)d_in[17];
    const float* e_w3   = (const float*)d_in[18];
    const float* e_b3   = (const float*)d_in[19];
    const float* s_w1   = (const float*)d_in[20];
    const float* s_b1   = (const float*)d_in[21];
    const float* s_w2   = (const float*)d_in[22];
    const float* s_b2   = (const float*)d_in[23];
    const float* s_w3   = (const float*)d_in[24];
    const float* s_b3   = (const float*)d_in[25];
    float* outp = (float*)d_out;

    float *p_q,*p_k,*p_v,*p_x2,*p_ln2,*p_t1,*p_h1;
    SYM(p_q, g_q); SYM(p_k, g_k); SYM(p_v, g_v);
    SYM(p_x2, g_x2); SYM(p_ln2, g_ln2); SYM(p_t1, g_t1); SYM(p_h1, g_h1);
    __half *lnH,*atH,*l2H,*hsH,*hhH;
    SYM(lnH, a_ln_h); SYM(atH, a_at_h); SYM(l2H, a_l2_h);
    SYM(hsH, a_hs_h); SYM(hhH, a_hh_h);
    __half *wqH,*wqL,*wkH,*wkL,*wvH,*wvL,*woH,*woL;
    __half *s1H,*s1L,*s3H,*s3L,*s2H,*s2L,*e1H,*e1L,*e3H,*e3L,*e2H,*e2L;
    SYM(wqH, w_q_h); SYM(wqL, w_q_l); SYM(wkH, w_k_h); SYM(wkL, w_k_l);
    SYM(wvH, w_v_h); SYM(wvL, w_v_l); SYM(woH, w_o_h); SYM(woL, w_o_l);
    SYM(s1H, w_s1_h); SYM(s1L, w_s1_l); SYM(s3H, w_s3_h); SYM(s3L, w_s3_l);
    SYM(s2H, w_s2_h); SYM(s2L, w_s2_l);
    SYM(e1H, w_e1_h); SYM(e1L, w_e1_l); SYM(e3H, w_e3_h); SYM(e3L, w_e3_l);
    SYM(e2H, w_e2_h); SYM(e2L, w_e2_l);

    cudaFuncSetAttribute(hgemm<0>, cudaFuncAttributeMaxDynamicSharedMemorySize, DSM);
    cudaFuncSetAttribute(hgemm<1>, cudaFuncAttributeMaxDynamicSharedMemorySize, DSM);
    cudaFuncSetAttribute(hgemm<2>, cudaFuncAttributeMaxDynamicSharedMemorySize, DSM);
    cudaFuncSetAttribute(hgemm<3>, cudaFuncAttributeMaxDynamicSharedMemorySize, DSM);

    // side stream: weight splits (overlap attention), then routed-expert up-chain
    // (overlaps shared-expert chain on the main stream).
    static cudaStream_t s1s = nullptr;
    static cudaEvent_t ev0 = nullptr, ev1 = nullptr, evr = nullptr, ev3 = nullptr;
    if (!s1s){
        cudaStreamCreateWithFlags(&s1s, cudaStreamNonBlocking);
        cudaEventCreateWithFlags(&ev0, cudaEventDisableTiming);
        cudaEventCreateWithFlags(&ev1, cudaEventDisableTiming);
        cudaEventCreateWithFlags(&evr, cudaEventDisableTiming);
        cudaEventCreateWithFlags(&ev3, cudaEventDisableTiming);
    }
    cudaEventRecord(ev0, 0);
    cudaStreamWaitEvent(s1s, ev0, 0);
    wsplitT<<<dim3(FSH/32, DM/32, 1), 256, 0, s1s>>>(s_w1, s1H, s1L, DM, FSH);
    wsplitT<<<dim3(FSH/32, DM/32, 1), 256, 0, s1s>>>(s_w3, s3H, s3L, DM, FSH);
    wsplitT<<<dim3(DM/32, FSH/32, 1), 256, 0, s1s>>>(s_w2, s2H, s2L, FSH, DM);
    wsplitT<<<dim3(FF/32, DM/32, NE), 256, 0, s1s>>>(e_w1, e1H, e1L, DM, FF);
    wsplitT<<<dim3(FF/32, DM/32, NE), 256, 0, s1s>>>(e_w3, e3H, e3L, DM, FF);
    wsplitT<<<dim3(DM/32, FF/32, NE), 256, 0, s1s>>>(e_w2, e2H, e2L, FF, DM);
    cudaEventRecord(ev1, s1s);

    // attention-path splits on main stream
    wsplitT<<<dim3(HDIM/32, DM/32, 1), 256>>>(wq_w, wqH, wqL, DM, HDIM);
    wsplitT<<<dim3(HDIM/32, DM/32, 1), 256>>>(wk_w, wkH, wkL, DM, HDIM);
    wsplitT<<<dim3(HDIM/32, DM/32, 1), 256>>>(wv_w, wvH, wvL, DM, HDIM);
    wsplitT<<<dim3(DM/32, HDIM/32, 1), 256>>>(wo_w, woH, woL, HDIM, DM);

    QKVH z3 = {};
    QKVH qkv;
    qkv.bh[0]=wqH; qkv.bh[1]=wkH; qkv.bh[2]=wvH;
    qkv.bl[0]=wqL; qkv.bl[1]=wkL; qkv.bl[2]=wvL;
    qkv.bias[0]=wq_b; qkv.bias[1]=wk_b; qkv.bias[2]=wv_b;
    qkv.c[0]=p_q; qkv.c[1]=p_k; qkv.c[2]=p_v;

    // ---- attention ----
    ln_kernel<<<SQ, 256>>>(x, attn_g, nullptr, lnH);
    hgemm<3><<<dim3(HDIM/128, SQ/128, 3), 256, DSM>>>(lnH, nullptr, nullptr,
        nullptr, nullptr, nullptr, nullptr, nullptr, HDIM, DM, qkv);
    score_kernel<<<dim3(SQ/64, SQ/64, NH), 256>>>(mask);
    softmax_kernel<<<NH*SQ, 256>>>();
    pv_kernel<<<dim3(DKV/64, SQ/64, NH), 256>>>();
    hgemm<0><<<dim3(DM/128, SQ/128), 256, DSM>>>(atH, woH, woL,
        wo_b, x, nullptr, p_x2, nullptr, DM, HDIM, z3);

    // ---- moe routing ----
    ln_kernel<<<SQ, 256>>>(p_x2, ffn_g, p_ln2, l2H);
    reset_kernel<<<1, 32>>>();
    gate_kernel<<<SQ, 256>>>(p_ln2, gate_w, gate_b);
    scanplace_kernel<<<1, 256>>>();
    cudaEventRecord(evr, 0);

    // ---- routed expert up-chain on side stream (overlaps shared chain) ----
    cudaStreamWaitEvent(s1s, evr, 0);
    hgemm<1><<<dim3(FF/128, SQ/128, NE), 256, DSM, s1s>>>(l2H, e1H, e1L,
        e_b1, nullptr, nullptr, p_h1, nullptr, FF, DM, z3);
    hgemm<1><<<dim3(FF/128, SQ/128, NE), 256, DSM, s1s>>>(l2H, e3H, e3L,
        e_b3, nullptr, p_h1, nullptr, hhH, FF, DM, z3);
    cudaEventRecord(ev3, s1s);

    // ---- shared expert on main stream ----
    cudaStreamWaitEvent(0, ev1, 0);
    hgemm<0><<<dim3(FSH/128, SQ/128), 256, DSM>>>(l2H, s1H, s1L,
        s_b1, nullptr, nullptr, p_t1, nullptr, FSH, DM, z3);
    hgemm<0><<<dim3(FSH/128, SQ/128), 256, DSM>>>(l2H, s3H, s3L,
        s_b3, nullptr, p_t1, nullptr, hsH, FSH, DM, z3);
    hgemm<0><<<dim3(DM/128, SQ/128), 256, DSM>>>(hsH, s2H, s2L,
        s_b2, p_x2, nullptr, outp, nullptr, DM, FSH, z3);

    // ---- routed expert down (after s2 store + e3 done) ----
    cudaStreamWaitEvent(0, ev3, 0);
    hgemm<2><<<dim3(DM/128, SQ/128, NE), 256, DSM>>>(hhH, e2H, e2L,
        e_b2, nullptr, nullptr, outp, nullptr, DM, FF, z3);
}